// round 4
// baseline (speedup 1.0000x reference)
#include <cuda_runtime.h>
#include <cuda_fp16.h>
#include <cstdint>
#include <cstddef>

// ---------------------------------------------------------------------------
// Problem constants
// ---------------------------------------------------------------------------
#define MDIM 4096
#define KDIM 4096
#define NDIM 12288
// GROUP = 64

// GEMM tiling
#define TM 128
#define TN 256
#define TKC 64
#define STAGES 4
#define KITERS (KDIM / TKC)           // 64
#define TILES_M (MDIM / TM)           // 32
#define TILES_N (NDIM / TN)           // 48
#define STAGE_BYTES 49152             // A 16K + B 32K
#define NTHREADS 256
// layout: [align slack 1024][stages 4*48K]
#define SMEM_TOTAL (1024 + STAGES * STAGE_BYTES)

// ---------------------------------------------------------------------------
// Scratch (device globals: no allocation allowed)
// ---------------------------------------------------------------------------
__device__ __half g_Xh[(size_t)MDIM * KDIM];   // 32 MB  fp16(X)
__device__ __half g_Wt[(size_t)NDIM * KDIM];   // 96 MB  W^T [N, K], K contiguous

// ---------------------------------------------------------------------------
// Prepass 1: fp16 conversion of X
// ---------------------------------------------------------------------------
__global__ void __launch_bounds__(256) split_x_kernel(const float4* __restrict__ x) {
    int i = blockIdx.x * blockDim.x + threadIdx.x;
    float4 v = x[i];
    __half2 h0 = __floats2half2_rn(v.x, v.y);
    __half2 h1 = __floats2half2_rn(v.z, v.w);
    __half2* xh = reinterpret_cast<__half2*>(g_Xh);
    xh[2 * i]     = h0;
    xh[2 * i + 1] = h1;
}

// ---------------------------------------------------------------------------
// Prepass 2: dequant q[K,N] (codes 0..3) -> fp16 W^T [N,K] via SMEM transpose
// w[k,n] = q[k,n]*scale[k/64,n] + zp[k/64,n]
// ---------------------------------------------------------------------------
__global__ void __launch_bounds__(256) dequant_kernel(const int* __restrict__ q,
                                                      const float* __restrict__ scale,
                                                      const float* __restrict__ zp) {
    __shared__ __half tile[32][34];
    const int n0 = blockIdx.x * 32;
    const int k0 = blockIdx.y * 32;   // 32 | 64 -> single group per k-tile
    const int tx = threadIdx.x;       // 0..31
    const int ty = threadIdx.y;       // 0..7
    const int g = k0 >> 6;
    const float s = scale[(size_t)g * NDIM + n0 + tx];
    const float z = zp[(size_t)g * NDIM + n0 + tx];
#pragma unroll
    for (int r = 0; r < 4; ++r) {
        int k = k0 + ty + r * 8;
        int qq = q[(size_t)k * NDIM + n0 + tx];
        tile[ty + r * 8][tx] = __float2half((float)qq * s + z);
    }
    __syncthreads();
#pragma unroll
    for (int r = 0; r < 4; ++r) {
        int n = n0 + ty + r * 8;
        g_Wt[(size_t)n * KDIM + k0 + tx] = tile[tx][ty + r * 8];
    }
}

// ---------------------------------------------------------------------------
// PTX helpers (compute_103-safe)
// ---------------------------------------------------------------------------
__device__ __forceinline__ uint32_t smem_u32(const void* p) {
    uint32_t a;
    asm("{ .reg .u64 t; cvta.to.shared.u64 t, %1; cvt.u32.u64 %0, t; }" : "=r"(a) : "l"(p));
    return a;
}

__device__ __forceinline__ void cp_async16(uint32_t dst, const void* src) {
    asm volatile("cp.async.cg.shared.global [%0], [%1], 16;" :: "r"(dst), "l"(src) : "memory");
}

__device__ __forceinline__ void cp_commit() {
    asm volatile("cp.async.commit_group;" ::: "memory");
}

__device__ __forceinline__ void cp_wait3() {
    asm volatile("cp.async.wait_group 3;" ::: "memory");
}

// Stage fill: A (128x64 fp16, 16KB) + B (256x64 fp16, 32KB), 128B rows, XOR swizzle
__device__ __forceinline__ void fill_stage(int kc, uint32_t stage_sm, int m0, int n0, int tid) {
    const size_t koff = (size_t)kc * TKC;
    const char* xh = (const char*)g_Xh;
    const char* wt = (const char*)g_Wt;
#pragma unroll
    for (int c = tid; c < 1024; c += NTHREADS) {      // A: 1024 chunks of 16B
        int row = c >> 3;
        uint32_t off = (uint32_t)c * 16;
        uint32_t sw = off ^ ((off >> 3) & 0x70);
        size_t gb = (((size_t)(m0 + row)) * KDIM + koff) * 2 + (size_t)(c & 7) * 16;
        cp_async16(stage_sm + sw, xh + gb);
    }
#pragma unroll
    for (int c = tid; c < 2048; c += NTHREADS) {      // B: 2048 chunks of 16B
        int row = c >> 3;
        uint32_t off = (uint32_t)c * 16;
        uint32_t sw = off ^ ((off >> 3) & 0x70);
        size_t gb = (((size_t)(n0 + row)) * KDIM + koff) * 2 + (size_t)(c & 7) * 16;
        cp_async16(stage_sm + 16384 + sw, wt + gb);
    }
}

// ---------------------------------------------------------------------------
// Main GEMM: out[M,N] = fp16(X)@W + bias, fp32 accumulate
// 8 warps, warp grid 2m x 4n, warp tile 64x64, mma.sync m16n8k16
// ---------------------------------------------------------------------------
__global__ void __launch_bounds__(NTHREADS, 1)
w2a16_gemm_kernel(const float* __restrict__ bias, float* __restrict__ out) {
    extern __shared__ char smem_raw[];
    uint32_t sb0 = smem_u32(smem_raw);
    uint32_t sb = (sb0 + 1023) & ~1023u;
    const uint32_t stage0 = sb;

    const int tid = threadIdx.x;
    const int wid = tid >> 5;
    const int lid = tid & 31;

    // Supertile raster (8 M-tiles per N column) for L2 reuse
    const int bid = blockIdx.x;
    const int rem = bid % (8 * TILES_N);
    const int m0 = ((bid / (8 * TILES_N)) * 8 + (rem & 7)) * TM;
    const int n0 = (rem >> 3) * TN;

    const int warp_m = wid & 1;        // 0..1 -> m offset 64*warp_m
    const int warp_n = wid >> 1;       // 0..3 -> n offset 64*warp_n

    float acc[4][8][4];
#pragma unroll
    for (int i = 0; i < 4; ++i)
#pragma unroll
        for (int j = 0; j < 8; ++j)
#pragma unroll
            for (int c = 0; c < 4; ++c) acc[i][j][c] = 0.f;

    // Prologue fills
#pragma unroll
    for (int s = 0; s < STAGES; ++s) {
        fill_stage(s, stage0 + s * STAGE_BYTES, m0, n0, tid);
        cp_commit();
    }

    // Per-lane ldmatrix addressing components (row * 128B)
    const uint32_t rbA = (uint32_t)(warp_m * 64 + (lid & 15)) * 128;
    const uint32_t colA = (uint32_t)((lid >> 4) * 16);        // +8 halves
    const uint32_t rbB = (uint32_t)(warp_n * 64 + ((lid >> 4) & 1) * 8 + (lid & 7)) * 128;
    const uint32_t colB = (uint32_t)(((lid >> 3) & 1) * 16);  // +8 halves

    for (int k = 0; k < KITERS; ++k) {
        const int s = k % STAGES;
        const uint32_t stage_sm = stage0 + s * STAGE_BYTES;

        cp_wait3();
        __syncthreads();

#pragma unroll
        for (int ks = 0; ks < 4; ++ks) {
            const uint32_t kb = (uint32_t)ks * 32;   // ks*16 halves

            // B fragments: 4 x4-ldmatrix -> 8 n-tiles (n8 each)
            uint32_t b0[4], b1[4], b2[4], b3[4];
            uint32_t* bt[4] = {b0, b1, b2, b3};
#pragma unroll
            for (int t = 0; t < 4; ++t) {
                uint32_t raw = rbB + (uint32_t)t * 2048 + kb + colB;
                uint32_t addr = stage_sm + 16384 + (raw ^ ((raw >> 3) & 0x70));
                asm volatile(
                    "ldmatrix.sync.aligned.m8n8.x4.shared.b16 {%0,%1,%2,%3}, [%4];"
                    : "=r"(bt[t][0]), "=r"(bt[t][1]), "=r"(bt[t][2]), "=r"(bt[t][3])
                    : "r"(addr));
            }

            // A fragments: 4 x4-ldmatrix -> 4 m16 tiles
            uint32_t a[4][4];
#pragma unroll
            for (int mt = 0; mt < 4; ++mt) {
                uint32_t raw = rbA + (uint32_t)mt * 2048 + kb + colA;
                uint32_t addr = stage_sm + (raw ^ ((raw >> 3) & 0x70));
                asm volatile(
                    "ldmatrix.sync.aligned.m8n8.x4.shared.b16 {%0,%1,%2,%3}, [%4];"
                    : "=r"(a[mt][0]), "=r"(a[mt][1]), "=r"(a[mt][2]), "=r"(a[mt][3])
                    : "r"(addr));
            }

#pragma unroll
            for (int mt = 0; mt < 4; ++mt) {
#pragma unroll
                for (int t = 0; t < 4; ++t) {
#pragma unroll
                    for (int half = 0; half < 2; ++half) {
                        const int ni = t * 2 + half;
                        float* c = acc[mt][ni];
                        uint32_t bb0 = bt[t][half * 2];
                        uint32_t bb1 = bt[t][half * 2 + 1];
                        asm volatile(
                            "mma.sync.aligned.m16n8k16.row.col.f32.f16.f16.f32 "
                            "{%0,%1,%2,%3}, {%4,%5,%6,%7}, {%8,%9}, {%0,%1,%2,%3};"
                            : "+f"(c[0]), "+f"(c[1]), "+f"(c[2]), "+f"(c[3])
                            : "r"(a[mt][0]), "r"(a[mt][1]), "r"(a[mt][2]), "r"(a[mt][3]),
                              "r"(bb0), "r"(bb1));
                    }
                }
            }
        }

        __syncthreads();
        const int nk = k + STAGES;
        if (nk < KITERS)
            fill_stage(nk, stage0 + s * STAGE_BYTES, m0, n0, tid);
        cp_commit();   // one group per iteration keeps wait_group math exact
    }

    // Epilogue: out = acc + bias
    const int mrow0 = m0 + warp_m * 64 + (lid >> 2);
    const int ncol0 = n0 + warp_n * 64 + (lid & 3) * 2;
#pragma unroll
    for (int mt = 0; mt < 4; ++mt) {
#pragma unroll
        for (int ni = 0; ni < 8; ++ni) {
            const int n = ncol0 + ni * 8;
            const float bx = bias[n];
            const float by = bias[n + 1];
            const int mA = mrow0 + mt * 16;
            float2 v0 = {acc[mt][ni][0] + bx, acc[mt][ni][1] + by};
            float2 v1 = {acc[mt][ni][2] + bx, acc[mt][ni][3] + by};
            *reinterpret_cast<float2*>(out + (size_t)mA * NDIM + n) = v0;
            *reinterpret_cast<float2*>(out + (size_t)(mA + 8) * NDIM + n) = v1;
        }
    }
}

// ---------------------------------------------------------------------------
// Launch
// ---------------------------------------------------------------------------
extern "C" void kernel_launch(void* const* d_in, const int* in_sizes, int n_in,
                              void* d_out, int out_size) {
    (void)in_sizes; (void)n_in; (void)out_size;
    const float* input   = (const float*)d_in[0];
    const int*   qweight = (const int*)d_in[1];
    const float* scale   = (const float*)d_in[2];
    const float* zp      = (const float*)d_in[3];
    const float* bias    = (const float*)d_in[4];
    float* out = (float*)d_out;

    cudaFuncSetAttribute(w2a16_gemm_kernel,
                         cudaFuncAttributeMaxDynamicSharedMemorySize, SMEM_TOTAL);

    split_x_kernel<<<(MDIM * (size_t)KDIM / 4) / 256, 256>>>(
        reinterpret_cast<const float4*>(input));
    dequant_kernel<<<dim3(NDIM / 32, KDIM / 32), dim3(32, 8)>>>(qweight, scale, zp);
    w2a16_gemm_kernel<<<TILES_M * TILES_N, NTHREADS, SMEM_TOTAL>>>(bias, out);
}